// round 5
// baseline (speedup 1.0000x reference)
#include <cuda_runtime.h>
#include <cuda_bf16.h>
#include <math.h>
#include <float.h>
#include <stdint.h>

// ---------------------------------------------------------------------------
// MultiLabelGCN on GB300 — split design:
//   agg_pack: BN+ReLU + skeleton aggregation, output pre-swizzled tf32
//             fragments (uint4 per lane = the 4 A-regs of one m16n8k8).
//   gemm_tc : pure tensor-core GEMM; A fragments via direct coalesced LDG,
//             W via cp.async double buffer; 1 barrier/chunk.
// ---------------------------------------------------------------------------

#define NUM_JOINTS 33
#define BATCH      4096
#define NN_ROWS    (BATCH * NUM_JOINTS)   // 135168
#define HDIM       256
#define NN_INV     (1.0f / 135168.0f)

#define PANELS 1024                 // NN_ROWS / 132
#define PROWS  132                  // 4 graphs per panel
#define PTILES 10                   // 160 padded rows = 10 x m16

// agg_pack smem bytes: sIn[132*132] + sNW[103]
#define ASMEM (132 * 132 * 4 + 103 * 4 + 4)
// gemm smem: B double buffer 2*256*40 u32 + stats 512 f
#define GSMEM (81920 + 2048)

__constant__ int ADJ_OFF[34] = {
    0,3,6,9,12,15,18,21,23,25,27,29,33,37,40,43,48,53,56,59,62,65,
    67,69,73,77,80,83,87,91,94,97,100,103};
__constant__ int ADJ_NB[103] = {
    1,4,0,  0,2,1,  1,3,2,  2,7,3,  0,5,4,  4,6,5,  5,8,6,  3,7,  6,8,
    10,9,  9,10,  12,13,23,11,  11,14,24,12,  11,15,13,  12,16,14,
    13,17,19,21,15,  14,18,20,22,16,  15,19,17,  16,20,18,  15,17,19,
    16,18,20,  15,21,  16,22,  11,24,25,23,  12,23,26,24,  23,27,25,
    24,28,26,  25,29,31,27,  26,30,32,28,  27,31,29,  28,32,30,
    29,27,31,  30,28,32};
__constant__ float DEGF[33] = {
    3,3,3,3,3,3,3,2,2,2,2,4,4,3,3,5,5,3,3,3,3,2,2,4,4,3,3,4,4,3,3,3,3};

// scratch
__device__ float g_bufA[(size_t)NN_ROWS * HDIM];
__device__ float g_bufB[(size_t)NN_ROWS * HDIM];
__device__ float g_stats[3 * 512];
__device__ uint2 g_wpack[4 * 8 * 256 * 16];                 // [mat][chunk][col][kp]
__device__ uint4 g_apack[(size_t)PANELS * 8 * PTILES * 4 * 32]; // [p][c][t][ks][lane]

// ---------------------------------------------------------------------------
__device__ __forceinline__ uint32_t f2tf32(float f) {
    uint32_t u;
    asm("cvt.rna.tf32.f32 %0, %1;" : "=r"(u) : "f"(f));
    return u;
}
__device__ __forceinline__ void mma_tf32(float* d, const uint32_t* a, const uint32_t* b) {
    asm volatile(
        "mma.sync.aligned.m16n8k8.row.col.f32.tf32.tf32.f32 "
        "{%0,%1,%2,%3}, {%4,%5,%6,%7}, {%8,%9}, {%0,%1,%2,%3};\n"
        : "+f"(d[0]), "+f"(d[1]), "+f"(d[2]), "+f"(d[3])
        : "r"(a[0]), "r"(a[1]), "r"(a[2]), "r"(a[3]), "r"(b[0]), "r"(b[1]));
}
__device__ __forceinline__ void cp16(void* dst, const void* src) {
    uint32_t d = (uint32_t)__cvta_generic_to_shared(dst);
    asm volatile("cp.async.cg.shared.global [%0], [%1], 16;\n" :: "r"(d), "l"(src));
}
#define CP_COMMIT() asm volatile("cp.async.commit_group;\n")
#define CP_WAIT0()  asm volatile("cp.async.wait_group 0;\n")

// ---------------------------------------------------------------------------
// pack weights -> tf32 pairs: [mat][chunk c0][col][kp], k = c0*32+(kp>>2)*8+(kp&3)
// ---------------------------------------------------------------------------
__global__ void pack_w(const float* __restrict__ w0, const float* __restrict__ w1,
                       const float* __restrict__ w2, const float* __restrict__ wh)
{
    int idx = blockIdx.x * blockDim.x + threadIdx.x;   // 0..131071
    int kp  = idx & 15;
    int col = (idx >> 4) & 255;
    int c0  = (idx >> 12) & 7;
    int m   = idx >> 15;
    const float* W = (m == 0) ? w0 : (m == 1) ? w1 : (m == 2) ? w2 : wh;
    int k = c0 * 32 + ((kp >> 2) * 8) + (kp & 3);
    uint2 v;
    v.x = f2tf32(W[(size_t)k * HDIM + col]);
    v.y = f2tf32(W[(size_t)(k + 4) * HDIM + col]);
    g_wpack[idx] = v;
}

__global__ void zero_stats_kernel(float* stats) {
    int i = blockIdx.x * blockDim.x + threadIdx.x;
    if (i < 3 * 512) stats[i] = 0.0f;
}

// ---------------------------------------------------------------------------
// agg_pack: grid (2, PANELS), block 256, dyn smem ASMEM.
// mode 0: nan_to_num(x); mode 1: BN(stats)+ReLU. Writes g_apack fragments.
// ---------------------------------------------------------------------------
__global__ void __launch_bounds__(256)
agg_pack(const float* __restrict__ in, const float* __restrict__ stats_in,
         const float* __restrict__ gam, const float* __restrict__ bet, int mode)
{
    extern __shared__ float sm[];
    float* sIn = sm;                 // [132 rows][stride 132]
    float* sNW = sm + 132 * 132;     // [103]

    const int tid = threadIdx.x, lane = tid & 31, warp = tid >> 5;
    const int p = blockIdx.y;
    const int h = blockIdx.x;        // channel half
    const int chBase = h * 128;

    if (tid < NUM_JOINTS) {
        float dn = rsqrtf(DEGF[tid]);
        for (int e = ADJ_OFF[tid]; e < ADJ_OFF[tid + 1]; e++)
            sNW[e] = dn * rsqrtf(DEGF[ADJ_NB[e]]);
    }

    // per-thread BN coefficients (its channel is fixed: tid & 127)
    const int ch = tid & 127;
    float scale = 1.0f, shift = 0.0f;
    if (mode == 1) {
        float mu  = stats_in[chBase + ch] * NN_INV;
        float ex2 = stats_in[256 + chBase + ch] * NN_INV;
        float inv = rsqrtf(ex2 - mu * mu + 1e-5f);
        scale = inv * gam[chBase + ch];
        shift = bet[chBase + ch] - mu * scale;
    }

    // load panel slice + pointwise transform
    const float* src = in + (size_t)p * PROWS * HDIM + chBase;
    for (int idx = tid; idx < PROWS * 128; idx += 256) {
        int r = idx >> 7;            // c == ch
        float f = src[(size_t)r * HDIM + ch];
        if (mode == 0) {
            if (isnan(f)) f = 0.0f;
            else if (isinf(f)) f = (f > 0.0f) ? FLT_MAX : -FLT_MAX;
        } else {
            f = fmaxf(fmaf(f, scale, shift), 0.0f);
        }
        sIn[r * 132 + ch] = f;
    }
    __syncthreads();

    // 160 fragment-write jobs: (cp 0..3, t 0..9, ks 0..3)
    uint4* outp = g_apack + (size_t)p * (8 * PTILES * 4 * 32);
    #pragma unroll 4
    for (int jj = 0; jj < 20; jj++) {
        int j   = warp + (jj << 3);
        int cp  = j / 40;
        int rem = j - cp * 40;
        int t   = rem >> 2;
        int ks  = rem & 3;
        int kl  = cp * 32 + ks * 8 + (lane & 3);
        int r0  = t * 16 + (lane >> 2);
        int r1  = r0 + 8;
        float a0 = 0.0f, a1 = 0.0f, a2 = 0.0f, a3 = 0.0f;
        if (r0 < PROWS) {
            int n = r0 % 33, gb = r0 - n;
            int e1 = ADJ_OFF[n + 1];
            for (int e = ADJ_OFF[n]; e < e1; e++) {
                float w = sNW[e];
                const float* b = &sIn[(gb + ADJ_NB[e]) * 132 + kl];
                a0 = fmaf(w, b[0], a0);
                a2 = fmaf(w, b[4], a2);
            }
        }
        if (r1 < PROWS) {
            int n = r1 % 33, gb = r1 - n;
            int e1 = ADJ_OFF[n + 1];
            for (int e = ADJ_OFF[n]; e < e1; e++) {
                float w = sNW[e];
                const float* b = &sIn[(gb + ADJ_NB[e]) * 132 + kl];
                a1 = fmaf(w, b[0], a1);
                a3 = fmaf(w, b[4], a3);
            }
        }
        uint4 v;
        v.x = f2tf32(a0); v.y = f2tf32(a1); v.z = f2tf32(a2); v.w = f2tf32(a3);
        int c = h * 4 + cp;          // global chunk
        outp[(((size_t)c * PTILES + t) * 4 + ks) * 32 + lane] = v;
    }
}

// ---------------------------------------------------------------------------
// gemm_tc: grid PANELS, block 512, dyn smem GSMEM. Full 256-col tile.
// A fragments via direct LDG from g_apack; W via cp.async double buffer.
// ---------------------------------------------------------------------------
__global__ void __launch_bounds__(512)
gemm_tc(int wsel, const float* __restrict__ bias, float* __restrict__ out,
        float* __restrict__ stats_out)
{
    extern __shared__ char smem[];
    uint32_t* sB2 = (uint32_t*)smem;              // [2][256*40] u32
    float* sStat  = (float*)(smem + 81920);       // [512]

    const int tid = threadIdx.x, lane = tid & 31, warp = tid >> 5;
    const int wm = warp >> 3, wn = warp & 7;
    const int p = blockIdx.x;

    sStat[tid] = 0.0f;

    const uint2* wbase = g_wpack + (size_t)wsel * (8 * 256 * 16);

    // issue W chunk 0
    #pragma unroll
    for (int i = 0; i < 4; i++) {
        int idx = tid + 512 * i;                  // 0..2047
        int col = idx >> 3, seg = idx & 7;
        cp16((char*)sB2 + col * 160 + seg * 16,
             (const char*)(wbase + ((size_t)col * 16 + seg * 2)));
    }
    CP_COMMIT();

    float acc[5][4][4];
    #pragma unroll
    for (int i = 0; i < 5; i++)
        #pragma unroll
        for (int nt = 0; nt < 4; nt++)
            #pragma unroll
            for (int j = 0; j < 4; j++) acc[i][nt][j] = 0.0f;

    const uint4* apB = g_apack + (size_t)p * (8 * PTILES * 4 * 32);

    for (int c = 0; c < 8; c++) {
        uint32_t* sBcur = sB2 + (c & 1) * 10240;
        CP_WAIT0();
        __syncthreads();              // W[c] ready; all warps retired MMA[c-1]
        if (c + 1 < 8) {
            uint32_t* sBn = sB2 + ((c + 1) & 1) * 10240;
            #pragma unroll
            for (int i = 0; i < 4; i++) {
                int idx = tid + 512 * i;
                int col = idx >> 3, seg = idx & 7;
                cp16((char*)sBn + col * 160 + seg * 16,
                     (const char*)(wbase + ((size_t)((c + 1) * 256 + col) * 16 + seg * 2)));
            }
            CP_COMMIT();
        }

        const uint4* ap = apB + (size_t)c * (PTILES * 4 * 32);
        #pragma unroll
        for (int ks = 0; ks < 4; ks++) {
            uint2 bfr[4];
            #pragma unroll
            for (int nt = 0; nt < 4; nt++) {
                int col_l = wn * 32 + nt * 8 + (lane >> 2);
                bfr[nt] = *(const uint2*)&sBcur[col_l * 40 + (ks * 4 + (lane & 3)) * 2];
            }
            #pragma unroll
            for (int i = 0; i < 5; i++) {
                uint4 av = ap[(((wm * 5 + i) * 4) + ks) * 32 + lane];
                const uint32_t* af = (const uint32_t*)&av;
                #pragma unroll
                for (int nt = 0; nt < 4; nt++)
                    mma_tf32(acc[i][nt], af, (const uint32_t*)&bfr[nt]);
            }
        }
    }

    // ---- epilogue ----
    float bval[8];
    #pragma unroll
    for (int nt = 0; nt < 4; nt++) {
        int col = wn * 32 + nt * 8 + 2 * (lane & 3);
        bval[nt * 2 + 0] = bias[col];
        bval[nt * 2 + 1] = bias[col + 1];
    }
    float cs1[8], cs2[8];
    #pragma unroll
    for (int j = 0; j < 8; j++) { cs1[j] = 0.0f; cs2[j] = 0.0f; }

    #pragma unroll
    for (int i = 0; i < 5; i++) {
        int rb = wm * 80 + i * 16 + (lane >> 2);
        #pragma unroll
        for (int nt = 0; nt < 4; nt++) {
            int col = wn * 32 + nt * 8 + 2 * (lane & 3);
            if (rb < PROWS) {
                float z0 = acc[i][nt][0] + bval[nt * 2 + 0];
                float z1 = acc[i][nt][1] + bval[nt * 2 + 1];
                *(float2*)(out + (size_t)(p * PROWS + rb) * HDIM + col) = make_float2(z0, z1);
                cs1[nt * 2 + 0] += z0; cs2[nt * 2 + 0] = fmaf(z0, z0, cs2[nt * 2 + 0]);
                cs1[nt * 2 + 1] += z1; cs2[nt * 2 + 1] = fmaf(z1, z1, cs2[nt * 2 + 1]);
            }
            int r2 = rb + 8;
            if (r2 < PROWS) {
                float z2 = acc[i][nt][2] + bval[nt * 2 + 0];
                float z3 = acc[i][nt][3] + bval[nt * 2 + 1];
                *(float2*)(out + (size_t)(p * PROWS + r2) * HDIM + col) = make_float2(z2, z3);
                cs1[nt * 2 + 0] += z2; cs2[nt * 2 + 0] = fmaf(z2, z2, cs2[nt * 2 + 0]);
                cs1[nt * 2 + 1] += z3; cs2[nt * 2 + 1] = fmaf(z3, z3, cs2[nt * 2 + 1]);
            }
        }
    }

    if (stats_out != nullptr) {
        #pragma unroll
        for (int j = 0; j < 8; j++) {
            int cl = wn * 32 + (j >> 1) * 8 + 2 * (lane & 3) + (j & 1);
            atomicAdd(&sStat[cl], cs1[j]);
            atomicAdd(&sStat[256 + cl], cs2[j]);
        }
        __syncthreads();
        if (tid < 256) {
            atomicAdd(&stats_out[tid], sStat[tid]);
            atomicAdd(&stats_out[256 + tid], sStat[256 + tid]);
        }
    }
}

// ---------------------------------------------------------------------------
// mean pool + classifier
// ---------------------------------------------------------------------------
__global__ void __launch_bounds__(256)
pool_kernel(const float* __restrict__ h, const float* __restrict__ wc,
            const float* __restrict__ bc, float* __restrict__ out)
{
    const int g = blockIdx.x;
    const int tid = threadIdx.x;
    const int lane = tid & 31, warp = tid >> 5;
    const size_t base = (size_t)g * NUM_JOINTS * HDIM;

    float s = 0.0f;
    #pragma unroll
    for (int n = 0; n < NUM_JOINTS; n++) s += h[base + n * HDIM + tid];
    s *= (1.0f / 33.0f);

    float4 wv = *(const float4*)(wc + tid * 4);
    float p0 = s * wv.x, p1 = s * wv.y, p2 = s * wv.z, p3 = s * wv.w;
    #pragma unroll
    for (int off = 16; off > 0; off >>= 1) {
        p0 += __shfl_down_sync(0xFFFFFFFF, p0, off);
        p1 += __shfl_down_sync(0xFFFFFFFF, p1, off);
        p2 += __shfl_down_sync(0xFFFFFFFF, p2, off);
        p3 += __shfl_down_sync(0xFFFFFFFF, p3, off);
    }
    __shared__ float4 part[8];
    if (lane == 0) part[warp] = make_float4(p0, p1, p2, p3);
    __syncthreads();
    if (tid == 0) {
        float4 t = make_float4(bc[0], bc[1], bc[2], bc[3]);
        #pragma unroll
        for (int w = 0; w < 8; w++) {
            t.x += part[w].x; t.y += part[w].y; t.z += part[w].z; t.w += part[w].w;
        }
        *(float4*)(out + g * 4) = t;
    }
}

// ---------------------------------------------------------------------------
extern "C" void kernel_launch(void* const* d_in, const int* in_sizes, int n_in,
                              void* d_out, int out_size)
{
    const float* x   = (const float*)d_in[0];
    const float* w0  = (const float*)d_in[1];
    const float* b0  = (const float*)d_in[2];
    const float* g0  = (const float*)d_in[3];
    const float* be0 = (const float*)d_in[4];
    const float* w1  = (const float*)d_in[5];
    const float* b1  = (const float*)d_in[6];
    const float* g1  = (const float*)d_in[7];
    const float* be1 = (const float*)d_in[8];
    const float* w2  = (const float*)d_in[9];
    const float* b2  = (const float*)d_in[10];
    const float* g2  = (const float*)d_in[11];
    const float* be2 = (const float*)d_in[12];
    const float* wh  = (const float*)d_in[13];
    const float* bh  = (const float*)d_in[14];
    const float* wc  = (const float*)d_in[15];
    const float* bc  = (const float*)d_in[16];

    float *bufA, *bufB, *stats;
    cudaGetSymbolAddress((void**)&bufA, g_bufA);
    cudaGetSymbolAddress((void**)&bufB, g_bufB);
    cudaGetSymbolAddress((void**)&stats, g_stats);

    cudaFuncSetAttribute(agg_pack, cudaFuncAttributeMaxDynamicSharedMemorySize, ASMEM);
    cudaFuncSetAttribute(gemm_tc,  cudaFuncAttributeMaxDynamicSharedMemorySize, GSMEM);

    pack_w<<<512, 256>>>(w0, w1, w2, wh);
    zero_stats_kernel<<<6, 256>>>(stats);

    dim3 ga(2, PANELS);

    agg_pack<<<ga, 256, ASMEM>>>(x, nullptr, nullptr, nullptr, 0);
    gemm_tc<<<PANELS, 512, GSMEM>>>(0, b0, bufB, stats);

    agg_pack<<<ga, 256, ASMEM>>>(bufB, stats, g0, be0, 1);
    gemm_tc<<<PANELS, 512, GSMEM>>>(1, b1, bufA, stats + 512);

    agg_pack<<<ga, 256, ASMEM>>>(bufA, stats + 512, g1, be1, 1);
    gemm_tc<<<PANELS, 512, GSMEM>>>(2, b2, bufB, stats + 1024);

    agg_pack<<<ga, 256, ASMEM>>>(bufB, stats + 1024, g2, be2, 1);
    gemm_tc<<<PANELS, 512, GSMEM>>>(3, bh, bufA, nullptr);

    pool_kernel<<<BATCH, 256>>>(bufA, wc, bc, (float*)d_out);
}

// round 6
// speedup vs baseline: 1.3954x; 1.3954x over previous
#include <cuda_runtime.h>
#include <cuda_bf16.h>
#include <math.h>
#include <float.h>
#include <stdint.h>

// ---------------------------------------------------------------------------
// MultiLabelGCN on GB300 — single fused kernel per layer:
//   cp.async double-buffered raw input chunk + packed-tf32 W chunk,
//   BN+ReLU folded into skeleton aggregation (smem->smem, tf32 fragments),
//   m16n8k8 tf32 MMA over full N=256 tile, stats in epilogue.
// ---------------------------------------------------------------------------

#define NUM_JOINTS 33
#define BATCH      4096
#define NN_ROWS    (BATCH * NUM_JOINTS)   // 135168
#define HDIM       256
#define NN_INV     (1.0f / 135168.0f)

#define PANELS 1024                 // NN_ROWS / 132
#define PROWS  132                  // 4 graphs per panel
#define MPAD   160                  // 10 x m16

// smem layout (bytes)
#define OFF_IN     0                        // float [2][132][36]   38016
#define OFF_A2     38016                    // u32 [160*40]         25600
#define OFF_B      63616                    // u32 [2][256*40]      81920
#define OFF_SCALE  145536                   // float [256]           1024
#define OFF_SHIFT  146560                   // float [256]           1024
#define OFF_STAT   147584                   // float [512]           2048
#define OFF_NW     149632                   // float [103] -> pad     512
#define SMEM_BYTES 150144

__constant__ int ADJ_OFF[34] = {
    0,3,6,9,12,15,18,21,23,25,27,29,33,37,40,43,48,53,56,59,62,65,
    67,69,73,77,80,83,87,91,94,97,100,103};
__constant__ int ADJ_NB[103] = {
    1,4,0,  0,2,1,  1,3,2,  2,7,3,  0,5,4,  4,6,5,  5,8,6,  3,7,  6,8,
    10,9,  9,10,  12,13,23,11,  11,14,24,12,  11,15,13,  12,16,14,
    13,17,19,21,15,  14,18,20,22,16,  15,19,17,  16,20,18,  15,17,19,
    16,18,20,  15,21,  16,22,  11,24,25,23,  12,23,26,24,  23,27,25,
    24,28,26,  25,29,31,27,  26,30,32,28,  27,31,29,  28,32,30,
    29,27,31,  30,28,32};
__constant__ float DEGF[33] = {
    3,3,3,3,3,3,3,2,2,2,2,4,4,3,3,5,5,3,3,3,3,2,2,4,4,3,3,4,4,3,3,3,3};

// scratch
__device__ float g_bufA[(size_t)NN_ROWS * HDIM];
__device__ float g_bufB[(size_t)NN_ROWS * HDIM];
__device__ float g_stats[3 * 512];
__device__ uint2 g_wpack[4 * 8 * 256 * 16];   // [mat][chunk][col][kp]

// ---------------------------------------------------------------------------
__device__ __forceinline__ uint32_t f2tf32(float f) {
    uint32_t u;
    asm("cvt.rna.tf32.f32 %0, %1;" : "=r"(u) : "f"(f));
    return u;
}
__device__ __forceinline__ void mma_tf32(float* d, const uint32_t* a, const uint32_t* b) {
    asm volatile(
        "mma.sync.aligned.m16n8k8.row.col.f32.tf32.tf32.f32 "
        "{%0,%1,%2,%3}, {%4,%5,%6,%7}, {%8,%9}, {%0,%1,%2,%3};\n"
        : "+f"(d[0]), "+f"(d[1]), "+f"(d[2]), "+f"(d[3])
        : "r"(a[0]), "r"(a[1]), "r"(a[2]), "r"(a[3]), "r"(b[0]), "r"(b[1]));
}
__device__ __forceinline__ void cp16(void* dst, const void* src) {
    uint32_t d = (uint32_t)__cvta_generic_to_shared(dst);
    asm volatile("cp.async.cg.shared.global [%0], [%1], 16;\n" :: "r"(d), "l"(src));
}
#define CP_COMMIT() asm volatile("cp.async.commit_group;\n")
#define CP_WAIT0()  asm volatile("cp.async.wait_group 0;\n")

// ---------------------------------------------------------------------------
// pack weights -> tf32 pairs: [mat][chunk c0][col][kp], k = c0*32+(kp>>2)*8+(kp&3)
// ---------------------------------------------------------------------------
__global__ void pack_w(const float* __restrict__ w0, const float* __restrict__ w1,
                       const float* __restrict__ w2, const float* __restrict__ wh)
{
    int idx = blockIdx.x * blockDim.x + threadIdx.x;   // 0..131071
    int kp  = idx & 15;
    int col = (idx >> 4) & 255;
    int c0  = (idx >> 12) & 7;
    int m   = idx >> 15;
    const float* W = (m == 0) ? w0 : (m == 1) ? w1 : (m == 2) ? w2 : wh;
    int k = c0 * 32 + ((kp >> 2) * 8) + (kp & 3);
    uint2 v;
    v.x = f2tf32(W[(size_t)k * HDIM + col]);
    v.y = f2tf32(W[(size_t)(k + 4) * HDIM + col]);
    g_wpack[idx] = v;
}

__global__ void zero_stats_kernel(float* stats) {
    int i = blockIdx.x * blockDim.x + threadIdx.x;
    if (i < 3 * 512) stats[i] = 0.0f;
}

// ---------------------------------------------------------------------------
// fused layer. grid = PANELS, block = 512, dyn smem SMEM_BYTES.
// mode 0: nan_to_num input; mode 1: BN(stats)+ReLU input.
// ---------------------------------------------------------------------------
__global__ void __launch_bounds__(512, 1)
fused_layer(const float* __restrict__ in, int wsel, const float* __restrict__ bias,
            float* __restrict__ out, const float* __restrict__ stats_in,
            const float* __restrict__ gam, const float* __restrict__ bet,
            float* __restrict__ stats_out, int mode)
{
    extern __shared__ char smem[];
    float*    sIn   = (float*)(smem + OFF_IN);     // [2][132][36]
    uint32_t* sA2   = (uint32_t*)(smem + OFF_A2);  // [160*40]
    uint32_t* sB2   = (uint32_t*)(smem + OFF_B);   // [2][256*40]
    float*    sScale= (float*)(smem + OFF_SCALE);
    float*    sShift= (float*)(smem + OFF_SHIFT);
    float*    sStat = (float*)(smem + OFF_STAT);
    float*    sNW   = (float*)(smem + OFF_NW);

    const int tid = threadIdx.x, lane = tid & 31, warp = tid >> 5;
    const int wm = warp >> 3, wn = warp & 7;
    const int p = blockIdx.x;
    const float* src = in + (size_t)p * PROWS * HDIM;
    const uint2* wbase = g_wpack + (size_t)wsel * (8 * 256 * 16);

    // ---- init (visible after first in-loop barrier) ----
    if (tid < NUM_JOINTS) {
        float dn = rsqrtf(DEGF[tid]);
        for (int e = ADJ_OFF[tid]; e < ADJ_OFF[tid + 1]; e++)
            sNW[e] = dn * rsqrtf(DEGF[ADJ_NB[e]]);
    }
    if (tid < 256) {
        if (mode == 1) {
            float mu  = stats_in[tid] * NN_INV;
            float ex2 = stats_in[256 + tid] * NN_INV;
            float inv = rsqrtf(ex2 - mu * mu + 1e-5f);
            float sc  = inv * gam[tid];
            sScale[tid] = sc;
            sShift[tid] = bet[tid] - mu * sc;
        } else {
            sScale[tid] = 1.0f;
            sShift[tid] = 0.0f;
        }
    }
    sStat[tid] = 0.0f;
    // zero pad rows of sA2 (rows 132..159, never rewritten)
    for (int i = tid; i < (MPAD - PROWS) * 40; i += 512)
        sA2[PROWS * 40 + i] = 0;

    // ---- prologue: cp.async chunk 0 (input + W) ----
    for (int j = tid; j < 1056; j += 512) {
        int r = j >> 3, seg = j & 7;
        cp16((char*)sIn + r * 144 + seg * 16,
             (const char*)(src + (size_t)r * HDIM + seg * 4));
    }
    for (int j = tid; j < 2048; j += 512) {
        int col = j >> 3, seg = j & 7;
        cp16((char*)sB2 + col * 160 + seg * 16,
             (const char*)(wbase + (size_t)col * 16 + seg * 2));
    }
    CP_COMMIT();

    float acc[5][4][4];
    #pragma unroll
    for (int i = 0; i < 5; i++)
        #pragma unroll
        for (int nt = 0; nt < 4; nt++)
            #pragma unroll
            for (int j = 0; j < 4; j++) acc[i][nt][j] = 0.0f;

    const int widx = ((lane >> 3) * 4 + (lane & 3)) * 2 + ((lane >> 2) & 1);

    for (int c = 0; c < 8; c++) {
        const int k0 = c * 32;
        CP_WAIT0();
        __syncthreads();   // chunk c staged; all warps retired MMA c-1 + agg c-1

        // issue chunk c+1 (safe: victim buffers last touched before this barrier)
        if (c + 1 < 8) {
            float* sInN = sIn + ((c + 1) & 1) * (132 * 36);
            const float* srcN = src + (c + 1) * 32;
            for (int j = tid; j < 1056; j += 512) {
                int r = j >> 3, seg = j & 7;
                cp16((char*)sInN + r * 144 + seg * 16,
                     (const char*)(srcN + (size_t)r * HDIM + seg * 4));
            }
            uint32_t* sBn = sB2 + ((c + 1) & 1) * 10240;
            const uint2* wbN = wbase + (size_t)(c + 1) * 256 * 16;
            for (int j = tid; j < 2048; j += 512) {
                int col = j >> 3, seg = j & 7;
                cp16((char*)sBn + col * 160 + seg * 16,
                     (const char*)(wbN + (size_t)col * 16 + seg * 2));
            }
            CP_COMMIT();
        }

        // ---- aggregate (BN+ReLU folded into reads) -> sA2 tf32 ----
        {
            const float* sInc = sIn + (c & 1) * (132 * 36);
            const float scl = sScale[k0 + lane];
            const float shf = sShift[k0 + lane];
            for (int r = warp; r < PROWS; r += 16) {
                int n  = r % NUM_JOINTS;
                int gb = r - n;
                float a = 0.0f;
                int e1 = ADJ_OFF[n + 1];
                for (int e = ADJ_OFF[n]; e < e1; e++) {
                    float f = sInc[(gb + ADJ_NB[e]) * 36 + lane];
                    if (mode == 0) {
                        if (isnan(f)) f = 0.0f;
                        else if (isinf(f)) f = (f > 0.0f) ? FLT_MAX : -FLT_MAX;
                    } else {
                        f = fmaxf(fmaf(f, scl, shf), 0.0f);
                    }
                    a = fmaf(sNW[e], f, a);
                }
                sA2[r * 40 + widx] = f2tf32(a);
            }
        }
        __syncthreads();   // sA2 ready

        // ---- MMA: 4 k8 steps from smem (conflict-free LDS.64) ----
        uint32_t* sBcur = sB2 + (c & 1) * 10240;
        #pragma unroll
        for (int ks = 0; ks < 4; ks++) {
            uint2 bfr[4];
            #pragma unroll
            for (int nt = 0; nt < 4; nt++) {
                int col_l = wn * 32 + nt * 8 + (lane >> 2);
                bfr[nt] = *(const uint2*)&sBcur[col_l * 40 + (ks * 4 + (lane & 3)) * 2];
            }
            #pragma unroll
            for (int i = 0; i < 5; i++) {
                int r = wm * 80 + i * 16 + (lane >> 2);
                uint2 p0 = *(const uint2*)&sA2[r * 40 + (ks * 4 + (lane & 3)) * 2];
                uint2 p1 = *(const uint2*)&sA2[(r + 8) * 40 + (ks * 4 + (lane & 3)) * 2];
                uint32_t af[4] = {p0.x, p1.x, p0.y, p1.y};
                #pragma unroll
                for (int nt = 0; nt < 4; nt++)
                    mma_tf32(acc[i][nt], af, (const uint32_t*)&bfr[nt]);
            }
        }
    }

    // ---- epilogue: bias, store, stats ----
    float bval[8];
    #pragma unroll
    for (int nt = 0; nt < 4; nt++) {
        int col = wn * 32 + nt * 8 + 2 * (lane & 3);
        bval[nt * 2 + 0] = bias[col];
        bval[nt * 2 + 1] = bias[col + 1];
    }
    float cs1[8], cs2[8];
    #pragma unroll
    for (int j = 0; j < 8; j++) { cs1[j] = 0.0f; cs2[j] = 0.0f; }

    #pragma unroll
    for (int i = 0; i < 5; i++) {
        int rb = wm * 80 + i * 16 + (lane >> 2);
        #pragma unroll
        for (int nt = 0; nt < 4; nt++) {
            int col = wn * 32 + nt * 8 + 2 * (lane & 3);
            if (rb < PROWS) {
                float z0 = acc[i][nt][0] + bval[nt * 2 + 0];
                float z1 = acc[i][nt][1] + bval[nt * 2 + 1];
                *(float2*)(out + (size_t)(p * PROWS + rb) * HDIM + col) = make_float2(z0, z1);
                cs1[nt * 2 + 0] += z0; cs2[nt * 2 + 0] = fmaf(z0, z0, cs2[nt * 2 + 0]);
                cs1[nt * 2 + 1] += z1; cs2[nt * 2 + 1] = fmaf(z1, z1, cs2[nt * 2 + 1]);
            }
            int r2 = rb + 8;
            if (r2 < PROWS) {
                float z2 = acc[i][nt][2] + bval[nt * 2 + 0];
                float z3 = acc[i][nt][3] + bval[nt * 2 + 1];
                *(float2*)(out + (size_t)(p * PROWS + r2) * HDIM + col) = make_float2(z2, z3);
                cs1[nt * 2 + 0] += z2; cs2[nt * 2 + 0] = fmaf(z2, z2, cs2[nt * 2 + 0]);
                cs1[nt * 2 + 1] += z3; cs2[nt * 2 + 1] = fmaf(z3, z3, cs2[nt * 2 + 1]);
            }
        }
    }

    if (stats_out != nullptr) {
        #pragma unroll
        for (int j = 0; j < 8; j++) {
            int cl = wn * 32 + (j >> 1) * 8 + 2 * (lane & 3) + (j & 1);
            atomicAdd(&sStat[cl], cs1[j]);
            atomicAdd(&sStat[256 + cl], cs2[j]);
        }
        __syncthreads();
        if (tid < 256) {
            atomicAdd(&stats_out[tid], sStat[tid]);
            atomicAdd(&stats_out[256 + tid], sStat[256 + tid]);
        }
    }
}

// ---------------------------------------------------------------------------
// mean pool + classifier
// ---------------------------------------------------------------------------
__global__ void __launch_bounds__(256)
pool_kernel(const float* __restrict__ h, const float* __restrict__ wc,
            const float* __restrict__ bc, float* __restrict__ out)
{
    const int g = blockIdx.x;
    const int tid = threadIdx.x;
    const int lane = tid & 31, warp = tid >> 5;
    const size_t base = (size_t)g * NUM_JOINTS * HDIM;

    float s = 0.0f;
    #pragma unroll
    for (int n = 0; n < NUM_JOINTS; n++) s += h[base + n * HDIM + tid];
    s *= (1.0f / 33.0f);

    float4 wv = *(const float4*)(wc + tid * 4);
    float p0 = s * wv.x, p1 = s * wv.y, p2 = s * wv.z, p3 = s * wv.w;
    #pragma unroll
    for (int off = 16; off > 0; off >>= 1) {
        p0 += __shfl_down_sync(0xFFFFFFFF, p0, off);
        p1 += __shfl_down_sync(0xFFFFFFFF, p1, off);
        p2 += __shfl_down_sync(0xFFFFFFFF, p2, off);
        p3 += __shfl_down_sync(0xFFFFFFFF, p3, off);
    }
    __shared__ float4 part[8];
    if (lane == 0) part[warp] = make_float4(p0, p1, p2, p3);
    __syncthreads();
    if (tid == 0) {
        float4 t = make_float4(bc[0], bc[1], bc[2], bc[3]);
        #pragma unroll
        for (int w = 0; w < 8; w++) {
            t.x += part[w].x; t.y += part[w].y; t.z += part[w].z; t.w += part[w].w;
        }
        *(float4*)(out + g * 4) = t;
    }
}

// ---------------------------------------------------------------------------
extern "C" void kernel_launch(void* const* d_in, const int* in_sizes, int n_in,
                              void* d_out, int out_size)
{
    const float* x   = (const float*)d_in[0];
    const float* w0  = (const float*)d_in[1];
    const float* b0  = (const float*)d_in[2];
    const float* g0  = (const float*)d_in[3];
    const float* be0 = (const float*)d_in[4];
    const float* w1  = (const float*)d_in[5];
    const float* b1  = (const float*)d_in[6];
    const float* g1  = (const float*)d_in[7];
    const float* be1 = (const float*)d_in[8];
    const float* w2  = (const float*)d_in[9];
    const float* b2  = (const float*)d_in[10];
    const float* g2  = (const float*)d_in[11];
    const float* be2 = (const float*)d_in[12];
    const float* wh  = (const float*)d_in[13];
    const float* bh  = (const float*)d_in[14];
    const float* wc  = (const float*)d_in[15];
    const float* bc  = (const float*)d_in[16];

    float *bufA, *bufB, *stats;
    cudaGetSymbolAddress((void**)&bufA, g_bufA);
    cudaGetSymbolAddress((void**)&bufB, g_bufB);
    cudaGetSymbolAddress((void**)&stats, g_stats);

    cudaFuncSetAttribute(fused_layer, cudaFuncAttributeMaxDynamicSharedMemorySize,
                         SMEM_BYTES);

    pack_w<<<512, 256>>>(w0, w1, w2, wh);
    zero_stats_kernel<<<6, 256>>>(stats);

    fused_layer<<<PANELS, 512, SMEM_BYTES>>>(x,    0, b0, bufB, nullptr, nullptr, nullptr, stats, 0);
    fused_layer<<<PANELS, 512, SMEM_BYTES>>>(bufB, 1, b1, bufA, stats,        g0, be0, stats + 512, 1);
    fused_layer<<<PANELS, 512, SMEM_BYTES>>>(bufA, 2, b2, bufB, stats + 512,  g1, be1, stats + 1024, 1);
    fused_layer<<<PANELS, 512, SMEM_BYTES>>>(bufB, 3, bh, bufA, stats + 1024, g2, be2, nullptr, 1);
    pool_kernel<<<BATCH, 256>>>(bufA, wc, bc, (float*)d_out);
}